// round 11
// baseline (speedup 1.0000x reference)
#include <cuda_runtime.h>
#include <math.h>
#include <stdint.h>

// Shape fixed by reference: x,y = [16, 3, 512, 512] f32
#define BATCH   16
#define HDIM    512
#define WDIM    512
#define RSTRIP  16                    // output rows per block
#define STRIPS  (HDIM / RSTRIP)       // 32
#define NBLOCKS (BATCH * STRIPS)      // 512
#define THREADS 256                   // warps 0-3 consume, warps 4-7 produce
#define ROWSIN  (RSTRIP + 6)          // 22 streamed rows
#define NS      4                     // smem ring slots (3 rows in flight)
#define SLOT_FLOATS (6 * WDIM)        // x0,x1,x2,y0,y1,y2 = 3072 floats = 12KB
#define EPSV    1e-6f

__device__ float        g_partials[NBLOCKS];
__device__ unsigned int g_count;     // zero-init at load; reset by last block

__device__ __forceinline__ void cpa16(uint32_t saddr, const float* gaddr, int srcsz) {
    asm volatile("cp.async.cg.shared.global [%0], [%1], 16, %2;"
                 :: "r"(saddr), "l"(gaddr), "r"(srcsz));
}
__device__ __forceinline__ void cp_commit() { asm volatile("cp.async.commit_group;"); }
__device__ __forceinline__ void cp_wait2()  { asm volatile("cp.async.wait_group 2;" ::: "memory"); }

__global__ __launch_bounds__(THREADS, 3) void charb_kernel(
    const float* __restrict__ x, const float* __restrict__ y,
    float* __restrict__ out)
{
    __shared__ float stage[NS * SLOT_FLOATS];   // 49152 B static (exactly 48 KB)
    // warpsum / isLast flag reuse 'stage' after the pipeline drains.

    const int tid  = threadIdx.x;
    const int lane = tid & 31;
    const int wid  = tid >> 5;
    const bool producer = (tid >= 128);
    const int  ptid = tid - 128;               // producer lane-column id (0..127)

    const int blk = blockIdx.x;
    const int b   = blk / STRIPS;
    const int s   = blk % STRIPS;
    const int h0  = s * RSTRIP;
    const bool rev = (s & 1);                  // serpentine: odd strips bottom-up
    const int rbase = rev ? (h0 + RSTRIP + 2) : (h0 - 3);
    const int rstep = rev ? -1 : 1;

    const size_t plane = (size_t)HDIM * WDIM;

    // ---- producer setup + prologue: issue rows 0..2 (one group each) ----
    const uint32_t sbase = (uint32_t)__cvta_generic_to_shared(stage);
    const float* xbp = x + (size_t)b * 3 * plane + (ptid << 2);
    const float* ybp = y + (size_t)b * 3 * plane + (ptid << 2);

    if (producer) {
        #pragma unroll
        for (int i = 0; i < 3; ++i) {
            const int r  = rbase + rstep * i;
            const bool ok = (r >= 0) && (r < HDIM);
            const int rc  = ok ? r : 0;
            const int sz  = ok ? 16 : 0;               // zfill out-of-image rows
            const uint32_t sa = sbase + (uint32_t)(i * SLOT_FLOATS * 4 + ptid * 16);
            const float* gx = xbp + (size_t)rc * WDIM;
            const float* gy = ybp + (size_t)rc * WDIM;
            cpa16(sa + 0 * 2048, gx,             sz);
            cpa16(sa + 1 * 2048, gx + plane,     sz);
            cpa16(sa + 2 * 2048, gx + 2 * plane, sz);
            cpa16(sa + 3 * 2048, gy,             sz);
            cpa16(sa + 4 * 2048, gy + plane,     sz);
            cpa16(sa + 5 * 2048, gy + 2 * plane, sz);
            cp_commit();
        }
    }

    // ---- consumer setup ----
    const int c0 = tid << 2;                   // consumer columns (tid < 128)
    const bool isL = (lane == 0);
    const bool isR = (lane == 31);
    const int  hc  = isL ? (c0 - 4) : (c0 + 4);
    const bool haloOk = (isL && c0 >= 4) || (isR && c0 + 4 < WDIM);

    const float4 z4 = make_float4(0.f, 0.f, 0.f, 0.f);
    float4 r0 = z4, r1 = z4, r2 = z4, r3 = z4, r4 = z4, r5 = z4;  // vertical ring
    float4 vs = z4;
    float  acc = 0.f;

    #pragma unroll 1
    for (int i = 0; i < ROWSIN; ++i) {
        if (producer) cp_wait2();    // group for row i complete (per-thread)
        __syncthreads();             // publishes row i to consumers; WAR gate

        if (!producer) {
            // ---- consume row i from slot i&3 (pure smem + math) ----
            const float* sp = stage + (i & (NS - 1)) * SLOT_FLOATS;
            const float4 xa = *(const float4*)(sp +    0 + c0);
            const float4 xm = *(const float4*)(sp +  512 + c0);
            const float4 xc = *(const float4*)(sp + 1024 + c0);
            const float4 ya = *(const float4*)(sp + 1536 + c0);
            const float4 ym = *(const float4*)(sp + 2048 + c0);
            const float4 yc = *(const float4*)(sp + 2560 + c0);

            float4 d;
            d.x = (xa.x - ya.x) + (xm.x - ym.x) + (xc.x - yc.x);
            d.y = (xa.y - ya.y) + (xm.y - ym.y) + (xc.y - yc.y);
            d.z = (xa.z - ya.z) + (xm.z - ym.z) + (xc.z - yc.z);
            d.w = (xa.w - ya.w) + (xm.w - ym.w) + (xc.w - yc.w);

            float4 dh = z4;
            if (haloOk) {
                const float* hp = sp + hc;
                const float4 ha = *(const float4*)(hp);
                const float4 hm = *(const float4*)(hp +  512);
                const float4 hv2= *(const float4*)(hp + 1024);
                const float4 pa = *(const float4*)(hp + 1536);
                const float4 pm = *(const float4*)(hp + 2048);
                const float4 pc = *(const float4*)(hp + 2560);
                dh.x = (ha.x - pa.x) + (hm.x - pm.x) + (hv2.x - pc.x);
                dh.y = (ha.y - pa.y) + (hm.y - pm.y) + (hv2.y - pc.y);
                dh.z = (ha.z - pa.z) + (hm.z - pm.z) + (hv2.z - pc.z);
                dh.w = (ha.w - pa.w) + (hm.w - pm.w) + (hv2.w - pc.w);
            }

            float py = __shfl_up_sync(0xffffffffu, d.y, 1);
            float pz = __shfl_up_sync(0xffffffffu, d.z, 1);
            float pw = __shfl_up_sync(0xffffffffu, d.w, 1);
            float nx = __shfl_down_sync(0xffffffffu, d.x, 1);
            float ny = __shfl_down_sync(0xffffffffu, d.y, 1);
            float nz = __shfl_down_sync(0xffffffffu, d.z, 1);
            if (isL) { py = dh.y; pz = dh.z; pw = dh.w; }
            if (isR) { nx = dh.x; ny = dh.y; nz = dh.z; }

            float4 hsum;
            hsum.x = ((py + pz) + (pw + d.x)) + ((d.y + d.z) + d.w);
            hsum.y = hsum.x - py + nx;
            hsum.z = hsum.y - pz + ny;
            hsum.w = hsum.z - pw + nz;

            vs.x += hsum.x; vs.y += hsum.y; vs.z += hsum.z; vs.w += hsum.w;
            if (i >= 6) {
                const float inv = 1.f / 49.f;
                const float v0 = vs.x * inv, v1 = vs.y * inv;
                const float v2 = vs.z * inv, v3 = vs.w * inv;
                acc += (sqrtf(v0 * v0 + EPSV) + sqrtf(v1 * v1 + EPSV))
                     + (sqrtf(v2 * v2 + EPSV) + sqrtf(v3 * v3 + EPSV));
                vs.x -= r0.x; vs.y -= r0.y; vs.z -= r0.z; vs.w -= r0.w;
            }
            r0 = r1; r1 = r2; r2 = r3; r3 = r4; r4 = r5; r5 = hsum;
        } else {
            // ---- produce row i+3 into slot (i+3)&3 == (i-1)&3 ----
            const int ni = i + 3;
            if (ni < ROWSIN) {
                const int r  = rbase + rstep * ni;
                const bool ok = (r >= 0) && (r < HDIM);
                const int rc  = ok ? r : 0;
                const int sz  = ok ? 16 : 0;
                const uint32_t sa = sbase + (uint32_t)((ni & (NS - 1)) * SLOT_FLOATS * 4 + ptid * 16);
                const float* gx = xbp + (size_t)rc * WDIM;
                const float* gy = ybp + (size_t)rc * WDIM;
                cpa16(sa + 0 * 2048, gx,             sz);
                cpa16(sa + 1 * 2048, gx + plane,     sz);
                cpa16(sa + 2 * 2048, gx + 2 * plane, sz);
                cpa16(sa + 3 * 2048, gy,             sz);
                cpa16(sa + 4 * 2048, gy + plane,     sz);
                cpa16(sa + 5 * 2048, gy + 2 * plane, sz);
            }
            cp_commit();             // uniform group accounting (may be empty)
        }
    }

    // ---- drain & reuse stage for reduction scratch ----
    __syncthreads();                 // all reads done; remaining groups are empty
    float* wsum = stage;             // [0..7] warp sums
    int*   flag = (int*)(stage + 8); // isLast

    #pragma unroll
    for (int off = 16; off; off >>= 1) acc += __shfl_xor_sync(0xffffffffu, acc, off);
    if (lane == 0) wsum[wid] = acc;  // producer warps contribute 0
    __syncthreads();
    if (tid < 32) {
        float v = (lane < 8) ? wsum[lane] : 0.f;
        v += __shfl_xor_sync(0xffffffffu, v, 4);
        v += __shfl_xor_sync(0xffffffffu, v, 2);
        v += __shfl_xor_sync(0xffffffffu, v, 1);
        if (tid == 0) {
            g_partials[blk] = v;
            __threadfence();
            const unsigned int t = atomicAdd(&g_count, 1u);
            *flag = (t == NBLOCKS - 1) ? 1 : 0;
        }
    }
    __syncthreads();

    // last-arriving block folds the 512 partials -> scalar (deterministic order)
    if (*flag) {
        __threadfence();
        float v = g_partials[tid] + g_partials[tid + 256];
        #pragma unroll
        for (int off = 16; off; off >>= 1) v += __shfl_xor_sync(0xffffffffu, v, off);
        if (lane == 0) wsum[wid] = v;
        __syncthreads();
        if (tid < 32) {
            float v2 = (lane < 8) ? wsum[lane] : 0.f;
            v2 += __shfl_xor_sync(0xffffffffu, v2, 4);
            v2 += __shfl_xor_sync(0xffffffffu, v2, 2);
            v2 += __shfl_xor_sync(0xffffffffu, v2, 1);
            if (tid == 0) {
                out[0]  = v2 / (float)((size_t)BATCH * HDIM * WDIM);
                g_count = 0u;
            }
        }
    }
}

extern "C" void kernel_launch(void* const* d_in, const int* in_sizes, int n_in,
                              void* d_out, int out_size)
{
    (void)in_sizes; (void)n_in; (void)out_size;
    const float* x = (const float*)d_in[0];
    const float* y = (const float*)d_in[1];
    float* out = (float*)d_out;

    charb_kernel<<<NBLOCKS, THREADS>>>(x, y, out);
}

// round 12
// speedup vs baseline: 1.6486x; 1.6486x over previous
#include <cuda_runtime.h>
#include <math.h>

// Shape fixed by reference: x,y = [16, 3, 512, 512] f32
#define BATCH   16
#define HDIM    512
#define WDIM    512
#define RSTRIP  8                     // output rows per block
#define STRIPS  (HDIM / RSTRIP)       // 64
#define NBLOCKS (BATCH * STRIPS)      // 1024
#define THREADS 128                   // one float4 column per thread
#define ROWSIN  (RSTRIP + 6)          // 14 streamed rows
#define EPSV    1e-6f

__device__ float        g_partials[NBLOCKS];
__device__ unsigned int g_count;     // zero-init at load; reset by last block

__global__ __launch_bounds__(THREADS, 7) void charb_kernel(
    const float* __restrict__ x, const float* __restrict__ y,
    float* __restrict__ out)
{
    __shared__ float drow[2][520];    // double-buffered diff row, halo-padded
    __shared__ float warpsum[4];
    __shared__ bool  isLast;

    const int tid  = threadIdx.x;
    const int lane = tid & 31;
    const int c0   = tid << 2;        // this thread's 4 columns

    const int blk = blockIdx.x;
    const int b   = blk / STRIPS;
    const int s   = blk % STRIPS;
    const int h0  = s * RSTRIP;
    const bool rev = (s & 1);         // serpentine: odd strips stream bottom-up
    const int rbase = rev ? (h0 + RSTRIP + 2) : (h0 - 3);
    const int rstep = rev ? -1 : 1;

    if (tid < 4) {                    // zero side halos of both buffers once
        drow[0][tid] = 0.f; drow[0][516 + tid] = 0.f;
        drow[1][tid] = 0.f; drow[1][516 + tid] = 0.f;
    }

    const size_t plane = (size_t)HDIM * WDIM;
    const float* xb = x + (size_t)b * 3 * plane + c0;
    const float* yb = y + (size_t)b * 3 * plane + c0;

    const float4 z4 = make_float4(0.f, 0.f, 0.f, 0.f);
    float4 a0 = z4, a1 = z4, a2 = z4, q0 = z4, q1 = z4, q2 = z4;

    {   // prologue: load stream row 0
        const int r = rbase;
        if (r >= 0 && r < HDIM) {
            const float* xp = xb + (size_t)r * WDIM;
            const float* yp = yb + (size_t)r * WDIM;
            a0 = *(const float4*)(xp);
            a1 = *(const float4*)(xp + plane);
            a2 = *(const float4*)(xp + 2 * plane);
            q0 = *(const float4*)(yp);
            q1 = *(const float4*)(yp + plane);
            q2 = *(const float4*)(yp + 2 * plane);
        }
    }

    // vertical register ring (6 previous hsum rows) + running 7-row sum
    float4 r0 = z4, r1 = z4, r2 = z4, r3 = z4, r4 = z4, r5 = z4;
    float4 vs = z4;
    float  acc = 0.f;

    #pragma unroll 1
    for (int i = 0; i < ROWSIN; ++i) {
        // channel-summed diff for row i -> drow[i&1]
        float4 d;
        d.x = (a0.x - q0.x) + (a1.x - q1.x) + (a2.x - q2.x);
        d.y = (a0.y - q0.y) + (a1.y - q1.y) + (a2.y - q2.y);
        d.z = (a0.z - q0.z) + (a1.z - q1.z) + (a2.z - q2.z);
        d.w = (a0.w - q0.w) + (a1.w - q1.w) + (a2.w - q2.w);
        *(float4*)&drow[i & 1][4 + c0] = d;

        // prefetch row i+1 (no consumer until next iteration)
        {
            const int ni = i + 1;
            const int nr = rbase + rstep * ni;
            const bool nv = (ni < ROWSIN) && (nr >= 0) && (nr < HDIM);
            a0 = z4; a1 = z4; a2 = z4; q0 = z4; q1 = z4; q2 = z4;
            if (nv) {
                const float* xp = xb + (size_t)nr * WDIM;
                const float* yp = yb + (size_t)nr * WDIM;
                a0 = *(const float4*)(xp);
                a1 = *(const float4*)(xp + plane);
                a2 = *(const float4*)(xp + 2 * plane);
                q0 = *(const float4*)(yp);
                q1 = *(const float4*)(yp + plane);
                q2 = *(const float4*)(yp + 2 * plane);
            }
        }

        __syncthreads();   // publishes drow[i&1]; WAR-gates buffer (i+1)&1
                           // (reads of buffer b at iter i complete before the
                           //  sync of iter i+1, which precedes its rewrite at i+2)

        // horizontal 7-tap sums via 3 aligned LDS.128
        float f[12];
        *(float4*)&f[0] = *(const float4*)&drow[i & 1][c0];
        *(float4*)&f[4] = *(const float4*)&drow[i & 1][c0 + 4];
        *(float4*)&f[8] = *(const float4*)&drow[i & 1][c0 + 8];
        float4 s4;
        s4.x = ((f[1] + f[2]) + (f[3] + f[4])) + ((f[5] + f[6]) + f[7]);
        s4.y = s4.x - f[1] + f[8];
        s4.z = s4.y - f[2] + f[9];
        s4.w = s4.z - f[3] + f[10];

        // vertical running 7-row sum + Charbonnier
        vs.x += s4.x; vs.y += s4.y; vs.z += s4.z; vs.w += s4.w;
        if (i >= 6) {
            const float inv = 1.f / 49.f;
            const float v0 = vs.x * inv, v1 = vs.y * inv;
            const float v2 = vs.z * inv, v3 = vs.w * inv;
            acc += (sqrtf(v0 * v0 + EPSV) + sqrtf(v1 * v1 + EPSV))
                 + (sqrtf(v2 * v2 + EPSV) + sqrtf(v3 * v3 + EPSV));
            vs.x -= r0.x; vs.y -= r0.y; vs.z -= r0.z; vs.w -= r0.w;
        }
        r0 = r1; r1 = r2; r2 = r3; r3 = r4; r4 = r5; r5 = s4;
    }

    // block reduction (4 warps)
    #pragma unroll
    for (int off = 16; off; off >>= 1) acc += __shfl_xor_sync(0xffffffffu, acc, off);
    if (lane == 0) warpsum[tid >> 5] = acc;
    __syncthreads();
    if (tid < 32) {
        float v = (lane < 4) ? warpsum[lane] : 0.f;
        v += __shfl_xor_sync(0xffffffffu, v, 2);
        v += __shfl_xor_sync(0xffffffffu, v, 1);
        if (tid == 0) {
            g_partials[blk] = v;
            __threadfence();
            const unsigned int t = atomicAdd(&g_count, 1u);
            isLast = (t == NBLOCKS - 1);
        }
    }
    __syncthreads();

    // last-arriving block folds the 1024 partials -> scalar (deterministic order)
    if (isLast) {
        __threadfence();
        float v = 0.f;
        #pragma unroll
        for (int k = 0; k < NBLOCKS / THREADS; ++k)
            v += g_partials[tid + k * THREADS];
        #pragma unroll
        for (int off = 16; off; off >>= 1) v += __shfl_xor_sync(0xffffffffu, v, off);
        if (lane == 0) warpsum[tid >> 5] = v;
        __syncthreads();
        if (tid < 32) {
            float v2 = (lane < 4) ? warpsum[lane] : 0.f;
            v2 += __shfl_xor_sync(0xffffffffu, v2, 2);
            v2 += __shfl_xor_sync(0xffffffffu, v2, 1);
            if (tid == 0) {
                out[0]  = v2 / (float)((size_t)BATCH * HDIM * WDIM);
                g_count = 0u;
            }
        }
    }
}

extern "C" void kernel_launch(void* const* d_in, const int* in_sizes, int n_in,
                              void* d_out, int out_size)
{
    (void)in_sizes; (void)n_in; (void)out_size;
    const float* x = (const float*)d_in[0];
    const float* y = (const float*)d_in[1];
    float* out = (float*)d_out;

    charb_kernel<<<NBLOCKS, THREADS>>>(x, y, out);
}

// round 13
// speedup vs baseline: 1.8520x; 1.1233x over previous
#include <cuda_runtime.h>
#include <math.h>

// Shape fixed by reference: x,y = [16, 3, 512, 512] f32
#define BATCH   16
#define HDIM    512
#define WDIM    512
#define RSTRIP  16                    // output rows per block
#define STRIPS  (HDIM / RSTRIP)       // 32
#define NBLOCKS (BATCH * STRIPS)      // 512
#define THREADS 128                   // one float4 column per thread
#define ROWSIN  (RSTRIP + 6)          // 22 streamed rows
#define ITERS   (ROWSIN / 2)          // 11 (2 rows per iteration)
#define EPSV    1e-6f

__device__ float        g_partials[NBLOCKS];
__device__ unsigned int g_count;     // zero-init at load; reset by last block

__global__ __launch_bounds__(THREADS, 4) void charb_kernel(
    const float* __restrict__ x, const float* __restrict__ y,
    float* __restrict__ out)
{
    __shared__ float drow[2][2][520]; // [bufset][row-of-pair], halo-padded
    __shared__ float warpsum[4];
    __shared__ bool  isLast;

    const int tid  = threadIdx.x;
    const int lane = tid & 31;
    const int c0   = tid << 2;        // this thread's 4 columns

    const int blk = blockIdx.x;
    const int b   = blk / STRIPS;
    const int s   = blk % STRIPS;
    const int h0  = s * RSTRIP;
    const bool rev = (s & 1);         // serpentine: odd strips stream bottom-up
    const int rbase = rev ? (h0 + RSTRIP + 2) : (h0 - 3);
    const int rstep = rev ? -1 : 1;

    if (tid < 4) {                    // zero side halos of all 4 buffers once
        drow[0][0][tid] = 0.f; drow[0][0][516 + tid] = 0.f;
        drow[0][1][tid] = 0.f; drow[0][1][516 + tid] = 0.f;
        drow[1][0][tid] = 0.f; drow[1][0][516 + tid] = 0.f;
        drow[1][1][tid] = 0.f; drow[1][1][516 + tid] = 0.f;
    }

    const size_t plane = (size_t)HDIM * WDIM;
    const float* xb = x + (size_t)b * 3 * plane + c0;
    const float* yb = y + (size_t)b * 3 * plane + c0;

    const float4 z4 = make_float4(0.f, 0.f, 0.f, 0.f);
    // two pipelined row-load sets (rows 2k and 2k+1 of the stream)
    float4 Aa0 = z4, Aa1 = z4, Aa2 = z4, Aq0 = z4, Aq1 = z4, Aq2 = z4;
    float4 Ba0 = z4, Ba1 = z4, Ba2 = z4, Bq0 = z4, Bq1 = z4, Bq2 = z4;

    {   // prologue: load stream rows 0 and 1
        const int rA = rbase;                   // i = 0
        if (rA >= 0 && rA < HDIM) {
            const float* xp = xb + (size_t)rA * WDIM;
            const float* yp = yb + (size_t)rA * WDIM;
            Aa0 = *(const float4*)(xp);
            Aa1 = *(const float4*)(xp + plane);
            Aa2 = *(const float4*)(xp + 2 * plane);
            Aq0 = *(const float4*)(yp);
            Aq1 = *(const float4*)(yp + plane);
            Aq2 = *(const float4*)(yp + 2 * plane);
        }
        const int rB = rbase + rstep;           // i = 1
        if (rB >= 0 && rB < HDIM) {
            const float* xp = xb + (size_t)rB * WDIM;
            const float* yp = yb + (size_t)rB * WDIM;
            Ba0 = *(const float4*)(xp);
            Ba1 = *(const float4*)(xp + plane);
            Ba2 = *(const float4*)(xp + 2 * plane);
            Bq0 = *(const float4*)(yp);
            Bq1 = *(const float4*)(yp + plane);
            Bq2 = *(const float4*)(yp + 2 * plane);
        }
    }

    // vertical register ring (6 previous hsum rows) + running 7-row sum
    float4 r0 = z4, r1 = z4, r2 = z4, r3 = z4, r4 = z4, r5 = z4;
    float4 vs = z4;
    float  acc = 0.f;

    #pragma unroll 1
    for (int it = 0; it < ITERS; ++it) {
        const int i0 = 2 * it;
        const int bs = it & 1;

        // channel-summed diffs for rows i0, i0+1 -> smem buffer set bs
        {
            float4 d;
            d.x = (Aa0.x - Aq0.x) + (Aa1.x - Aq1.x) + (Aa2.x - Aq2.x);
            d.y = (Aa0.y - Aq0.y) + (Aa1.y - Aq1.y) + (Aa2.y - Aq2.y);
            d.z = (Aa0.z - Aq0.z) + (Aa1.z - Aq1.z) + (Aa2.z - Aq2.z);
            d.w = (Aa0.w - Aq0.w) + (Aa1.w - Aq1.w) + (Aa2.w - Aq2.w);
            *(float4*)&drow[bs][0][4 + c0] = d;
        }
        {
            float4 d;
            d.x = (Ba0.x - Bq0.x) + (Ba1.x - Bq1.x) + (Ba2.x - Bq2.x);
            d.y = (Ba0.y - Bq0.y) + (Ba1.y - Bq1.y) + (Ba2.y - Bq2.y);
            d.z = (Ba0.z - Bq0.z) + (Ba1.z - Bq1.z) + (Ba2.z - Bq2.z);
            d.w = (Ba0.w - Bq0.w) + (Ba1.w - Bq1.w) + (Ba2.w - Bq2.w);
            *(float4*)&drow[bs][1][4 + c0] = d;
        }

        // prefetch rows i0+2, i0+3 (12 independent LDG.128 in flight)
        {
            const int niA = i0 + 2;
            const int nrA = rbase + rstep * niA;
            const bool vA = (niA < ROWSIN) && (nrA >= 0) && (nrA < HDIM);
            Aa0 = z4; Aa1 = z4; Aa2 = z4; Aq0 = z4; Aq1 = z4; Aq2 = z4;
            if (vA) {
                const float* xp = xb + (size_t)nrA * WDIM;
                const float* yp = yb + (size_t)nrA * WDIM;
                Aa0 = *(const float4*)(xp);
                Aa1 = *(const float4*)(xp + plane);
                Aa2 = *(const float4*)(xp + 2 * plane);
                Aq0 = *(const float4*)(yp);
                Aq1 = *(const float4*)(yp + plane);
                Aq2 = *(const float4*)(yp + 2 * plane);
            }
            const int niB = i0 + 3;
            const int nrB = rbase + rstep * niB;
            const bool vB = (niB < ROWSIN) && (nrB >= 0) && (nrB < HDIM);
            Ba0 = z4; Ba1 = z4; Ba2 = z4; Bq0 = z4; Bq1 = z4; Bq2 = z4;
            if (vB) {
                const float* xp = xb + (size_t)nrB * WDIM;
                const float* yp = yb + (size_t)nrB * WDIM;
                Ba0 = *(const float4*)(xp);
                Ba1 = *(const float4*)(xp + plane);
                Ba2 = *(const float4*)(xp + 2 * plane);
                Bq0 = *(const float4*)(yp);
                Bq1 = *(const float4*)(yp + plane);
                Bq2 = *(const float4*)(yp + 2 * plane);
            }
        }

        __syncthreads();   // publishes both rows of bufset bs; WAR gate
                           // (reads of bufset b at iter it finish before the
                           //  sync of it+1, which precedes its rewrite at it+2)

        // ---- row i0: horizontal 7-tap + vertical update ----
        {
            float f[12];
            *(float4*)&f[0] = *(const float4*)&drow[bs][0][c0];
            *(float4*)&f[4] = *(const float4*)&drow[bs][0][c0 + 4];
            *(float4*)&f[8] = *(const float4*)&drow[bs][0][c0 + 8];
            float4 s4;
            s4.x = ((f[1] + f[2]) + (f[3] + f[4])) + ((f[5] + f[6]) + f[7]);
            s4.y = s4.x - f[1] + f[8];
            s4.z = s4.y - f[2] + f[9];
            s4.w = s4.z - f[3] + f[10];

            vs.x += s4.x; vs.y += s4.y; vs.z += s4.z; vs.w += s4.w;
            if (i0 >= 6) {
                const float inv = 1.f / 49.f;
                const float v0 = vs.x * inv, v1 = vs.y * inv;
                const float v2 = vs.z * inv, v3 = vs.w * inv;
                acc += (sqrtf(v0 * v0 + EPSV) + sqrtf(v1 * v1 + EPSV))
                     + (sqrtf(v2 * v2 + EPSV) + sqrtf(v3 * v3 + EPSV));
                vs.x -= r0.x; vs.y -= r0.y; vs.z -= r0.z; vs.w -= r0.w;
            }
            r0 = r1; r1 = r2; r2 = r3; r3 = r4; r4 = r5; r5 = s4;
        }

        // ---- row i0+1 ----
        {
            float f[12];
            *(float4*)&f[0] = *(const float4*)&drow[bs][1][c0];
            *(float4*)&f[4] = *(const float4*)&drow[bs][1][c0 + 4];
            *(float4*)&f[8] = *(const float4*)&drow[bs][1][c0 + 8];
            float4 s4;
            s4.x = ((f[1] + f[2]) + (f[3] + f[4])) + ((f[5] + f[6]) + f[7]);
            s4.y = s4.x - f[1] + f[8];
            s4.z = s4.y - f[2] + f[9];
            s4.w = s4.z - f[3] + f[10];

            vs.x += s4.x; vs.y += s4.y; vs.z += s4.z; vs.w += s4.w;
            if (i0 + 1 >= 6) {
                const float inv = 1.f / 49.f;
                const float v0 = vs.x * inv, v1 = vs.y * inv;
                const float v2 = vs.z * inv, v3 = vs.w * inv;
                acc += (sqrtf(v0 * v0 + EPSV) + sqrtf(v1 * v1 + EPSV))
                     + (sqrtf(v2 * v2 + EPSV) + sqrtf(v3 * v3 + EPSV));
                vs.x -= r0.x; vs.y -= r0.y; vs.z -= r0.z; vs.w -= r0.w;
            }
            r0 = r1; r1 = r2; r2 = r3; r3 = r4; r4 = r5; r5 = s4;
        }
    }

    // block reduction (4 warps)
    #pragma unroll
    for (int off = 16; off; off >>= 1) acc += __shfl_xor_sync(0xffffffffu, acc, off);
    if (lane == 0) warpsum[tid >> 5] = acc;
    __syncthreads();
    if (tid < 32) {
        float v = (lane < 4) ? warpsum[lane] : 0.f;
        v += __shfl_xor_sync(0xffffffffu, v, 2);
        v += __shfl_xor_sync(0xffffffffu, v, 1);
        if (tid == 0) {
            g_partials[blk] = v;
            __threadfence();
            const unsigned int t = atomicAdd(&g_count, 1u);
            isLast = (t == NBLOCKS - 1);
        }
    }
    __syncthreads();

    // last-arriving block folds the 512 partials -> scalar (deterministic order)
    if (isLast) {
        __threadfence();
        float v = 0.f;
        #pragma unroll
        for (int k = 0; k < NBLOCKS / THREADS; ++k)
            v += g_partials[tid + k * THREADS];
        #pragma unroll
        for (int off = 16; off; off >>= 1) v += __shfl_xor_sync(0xffffffffu, v, off);
        if (lane == 0) warpsum[tid >> 5] = v;
        __syncthreads();
        if (tid < 32) {
            float v2 = (lane < 4) ? warpsum[lane] : 0.f;
            v2 += __shfl_xor_sync(0xffffffffu, v2, 2);
            v2 += __shfl_xor_sync(0xffffffffu, v2, 1);
            if (tid == 0) {
                out[0]  = v2 / (float)((size_t)BATCH * HDIM * WDIM);
                g_count = 0u;
            }
        }
    }
}

extern "C" void kernel_launch(void* const* d_in, const int* in_sizes, int n_in,
                              void* d_out, int out_size)
{
    (void)in_sizes; (void)n_in; (void)out_size;
    const float* x = (const float*)d_in[0];
    const float* y = (const float*)d_in[1];
    float* out = (float*)d_out;

    charb_kernel<<<NBLOCKS, THREADS>>>(x, y, out);
}